// round 15
// baseline (speedup 1.0000x reference)
#include <cuda_runtime.h>
#include <cuda_fp16.h>
#include <cstdint>

// Problem constants
#define M_TOK   131072      // b*s*a = 2*32*2048
#define EMB     512
#define NHEAD   8
#define HDIM    64
#define NGROUP  512         // b*s*h = 64*8
#define ALEN    2048
#define EPS_F   1e-6f

// Scratch (device globals: allocation-free per harness rules)
__device__ __half   g_iqh[(size_t)M_TOK * EMB];
__device__ __half   g_ikh[(size_t)M_TOK * EMB];
__device__ __half   g_Qh [(size_t)M_TOK * EMB];
__device__ __half   g_Kh [(size_t)M_TOK * EMB];
__device__ __half   g_Vh [(size_t)M_TOK * EMB];
__device__ __half   g_AOh[(size_t)M_TOK * EMB];
__device__ uint32_t g_KtVh[(size_t)NGROUP * 2304];  // packed fp16 [g][d2(32)][e(72)]
__device__ __half   g_Whf[4 * (size_t)EMB * EMB];   // fp16 weights, plain [K][N]

// ---------------------------------------------------------------------------
__device__ __forceinline__ void mma16(float* d, const uint32_t* a, const uint32_t* b) {
    asm volatile(
        "mma.sync.aligned.m16n8k16.row.col.f32.f16.f16.f32 "
        "{%0,%1,%2,%3},{%4,%5,%6,%7},{%8,%9},{%0,%1,%2,%3};"
        : "+f"(d[0]), "+f"(d[1]), "+f"(d[2]), "+f"(d[3])
        : "r"(a[0]), "r"(a[1]), "r"(a[2]), "r"(a[3]),
          "r"(b[0]), "r"(b[1]));
}

__device__ __forceinline__ void ldmx4(uint32_t* r, uint32_t addr) {
    asm volatile("ldmatrix.sync.aligned.m8n8.x4.shared.b16 {%0,%1,%2,%3}, [%4];"
                 : "=r"(r[0]), "=r"(r[1]), "=r"(r[2]), "=r"(r[3]) : "r"(addr));
}
__device__ __forceinline__ void ldmx4t(uint32_t* r, uint32_t addr) {
    asm volatile("ldmatrix.sync.aligned.m8n8.x4.trans.shared.b16 {%0,%1,%2,%3}, [%4];"
                 : "=r"(r[0]), "=r"(r[1]), "=r"(r[2]), "=r"(r[3]) : "r"(addr));
}
__device__ __forceinline__ void ldmx2t(uint32_t* r, uint32_t addr) {
    asm volatile("ldmatrix.sync.aligned.m8n8.x2.trans.shared.b16 {%0,%1}, [%2];"
                 : "=r"(r[0]), "=r"(r[1]) : "r"(addr));
}

__device__ __forceinline__ uint32_t smem_u32(const void* p) {
    uint32_t a;
    asm("{ .reg .u64 t; cvta.to.shared.u64 t, %1; cvt.u32.u64 %0, t; }"
        : "=r"(a) : "l"(p));
    return a;
}

__device__ __forceinline__ void cp16(uint32_t dst, const void* src) {
    asm volatile("cp.async.cg.shared.global [%0], [%1], 16;"
                 :: "r"(dst), "l"(src) : "memory");
}
#define CP_COMMIT() asm volatile("cp.async.commit_group;" ::: "memory")
#define CP_WAIT1()  asm volatile("cp.async.wait_group 1;" ::: "memory")
#define CP_WAIT0()  asm volatile("cp.async.wait_group 0;" ::: "memory")

__device__ __forceinline__ uint32_t packh2(float a, float b) {
    __half2 h = __floats2half2_rn(a, b);
    return *(uint32_t*)&h;
}
__device__ __forceinline__ float elu1(float v) {
    return v > 0.f ? v + 1.f : expf(v);
}

// Fragment mapping (m16n8k16, validated):
//   A: lane l, reg rg: pairs A[(l>>2)+8*(rg&1)][(l&3)*2 + 8*(rg>>1) + {0,1}]
//   B: lane l, reg rg: pairs B[k=(l&3)*2+8*rg+{0,1}][n=(l>>2)]
//   C: lane l, reg c:  row=(l>>2)+8*(c>>1), col=(l&3)*2+(c&1)
// ldmx4t on k-major [k][n] rows yields two n-tiles' B fragments per call
// (validated by ktv_mma since R7).

// ===========================================================================
// Prep: fp32 -> fp16 for both inputs in ONE launch
// ===========================================================================
#define APREP_BLKS_PER 32768
__global__ __launch_bounds__(256)
void aprep2_kernel(const float* __restrict__ s0, __half* __restrict__ d0,
                   const float* __restrict__ s1, __half* __restrict__ d1)
{
    const int b = blockIdx.x;
    const float* src = (b < APREP_BLKS_PER) ? s0 : s1;
    __half*      dst = (b < APREP_BLKS_PER) ? d0 : d1;
    const size_t i = ((size_t)(b & (APREP_BLKS_PER - 1)) * 256 + threadIdx.x) * 8;
    const float4 a = *(const float4*)(src + i);
    const float4 c = *(const float4*)(src + i + 4);
    __half2 h[4];
    h[0] = __floats2half2_rn(a.x, a.y);
    h[1] = __floats2half2_rn(a.z, a.w);
    h[2] = __floats2half2_rn(c.x, c.y);
    h[3] = __floats2half2_rn(c.z, c.w);
    *(uint4*)(dst + i) = *(uint4*)h;
}

// ===========================================================================
// Weight prep — plain fp32 -> fp16, all 4 weights, one launch (grid 1024)
// ===========================================================================
__global__ __launch_bounds__(256)
void wprep4_kernel(const float* __restrict__ W0, const float* __restrict__ W1,
                   const float* __restrict__ W2, const float* __restrict__ W3,
                   __half* __restrict__ Wh)
{
    const int id = blockIdx.x * 256 + threadIdx.x;   // 0..262143 (float4 units)
    const int w  = id >> 16;                          // 0..3
    const int o  = id & 65535;
    const float* W = (w == 0) ? W0 : (w == 1) ? W1 : (w == 2) ? W2 : W3;
    const float4 v = ((const float4*)W)[o];
    uint2 out;
    out.x = packh2(v.x, v.y);
    out.y = packh2(v.z, v.w);
    ((uint2*)(Wh + (size_t)w * EMB * EMB))[o] = out;
}

// ===========================================================================
// Shared GEMM config: 3-stage, 32x64 warp tile, B via ldmatrix.trans.
// A stage: 128 rows x 144B. B stage: 64 k-rows x 272B (256B data + 16B pad;
// stride/4 = 68 ≡ 4 mod 32 -> 8-row ldmatrix walk hits all 32 banks).
// ===========================================================================
#define AS_B    144
#define A_STG   (128 * 36)            // 4608 words
#define BS_B    272                   // B row stride bytes
#define B_STG   4352                  // words (64 * 272 / 4)
#define STG_W   (A_STG + B_STG)       // 8960 words
#define GEMM_SMEM (3 * STG_W * 4)     // 107520 B; 2 CTAs fit

// ===========================================================================
// MERGED Q/K/V projection GEMM — one launch, grid.x = 12.
//   w = bx>>2 : 0 -> Q (A=iqh, Wq, bq, out Qh, elu+1)
//               1 -> K (A=ikh, Wk, bk, out Kh, elu+1)
//               2 -> V (A=ikh, Wv, bv, out Vh, identity)
// ===========================================================================
__global__ __launch_bounds__(256, 2)
void gemm_qkv_kernel(const __half* __restrict__ iq,
                     const __half* __restrict__ ik,
                     const __half* __restrict__ WhBase,
                     const float* __restrict__ bq,
                     const float* __restrict__ bk,
                     const float* __restrict__ bv,
                     __half* __restrict__ Qo,
                     __half* __restrict__ Ko,
                     __half* __restrict__ Vo)
{
    extern __shared__ uint32_t sm[];
    const uint32_t smb = smem_u32(sm);

    const int t   = threadIdx.x;
    const int lid = t & 31;
    const int wid = t >> 5;
    const int wr  = wid >> 1;
    const int wc  = wid & 1;
    const int bxr = blockIdx.x;          // 0..11
    const int w   = bxr >> 2;            // 0..2
    const int bx  = bxr & 3;
    const int bm  = blockIdx.y * 128;

    const __half* Ah  = (w == 0) ? iq : ik;
    const __half* Wh  = WhBase + (size_t)w * EMB * EMB;
    const float* bias = (w == 0) ? bq : (w == 1) ? bk : bv;
    __half* Cv        = (w == 0) ? Qo : (w == 1) ? Ko : Vo;
    const int act     = (w < 2);

    auto issue = [&](int c, int s) {
        const uint32_t st = smb + (uint32_t)s * (STG_W * 4);
        // A: 128 rows x 64 fp16 = 1024 x 16B
        #pragma unroll
        for (int i = 0; i < 4; i++) {
            const int id  = t + i * 256;
            const int row = id >> 3;
            const int j   = id & 7;
            cp16(st + row * AS_B + j * 16,
                 Ah + (size_t)(bm + row) * EMB + c * 64 + j * 8);
        }
        // B: 64 k-rows x 128 n (bx slice) = 1024 x 16B, rows at stride 272B
        const uint32_t stB = st + A_STG * 4;
        #pragma unroll
        for (int i = 0; i < 4; i++) {
            const int id  = t + i * 256;
            const int row = id >> 4;         // 0..63
            const int j   = id & 15;         // 0..15
            cp16(stB + row * BS_B + j * 16,
                 Wh + (size_t)(c * 64 + row) * EMB + bx * 128 + j * 8);
        }
        CP_COMMIT();
    };

    float acc[2][8][4];
    #pragma unroll
    for (int i = 0; i < 2; i++)
        #pragma unroll
        for (int j = 0; j < 8; j++)
            #pragma unroll
            for (int k = 0; k < 4; k++)
                acc[i][j][k] = 0.f;

    // ldmatrix.trans lane address components (validated ktv pattern)
    const int g2 = lid >> 3;
    const int l8 = lid & 7;
    const int b_row = (g2 & 1) * 8 + l8;     // k within 16
    const int b_col = (g2 >> 1) * 8;         // n within 16

    issue(0, 0);
    issue(1, 1);

    for (int c = 0; c < 8; c++) {
        const int s = c % 3;
        if (c >= 6) { CP_WAIT0(); } else { CP_WAIT1(); }
        __syncthreads();
        if (c + 2 < 8) issue(c + 2, (c + 2) % 3);

        const uint32_t stA = smb + (uint32_t)s * (STG_W * 4);
        const uint32_t stB = stA + A_STG * 4;

        #pragma unroll
        for (int ks = 0; ks < 4; ks++) {
            uint32_t aF[2][4];
            #pragma unroll
            for (int m2 = 0; m2 < 2; m2++)
                ldmx4(aF[m2], stA + (wr * 32 + m2 * 16 + (lid & 15)) * AS_B
                               + ks * 32 + (lid >> 4) * 16);
            #pragma unroll
            for (int np = 0; np < 4; np++) {
                uint32_t r4[4];
                ldmx4t(r4, stB + (ks * 16 + b_row) * BS_B
                             + (wc * 64 + np * 16 + b_col) * 2);
                mma16(acc[0][2 * np],     aF[0], r4);
                mma16(acc[0][2 * np + 1], aF[0], r4 + 2);
                mma16(acc[1][2 * np],     aF[1], r4);
                mma16(acc[1][2 * np + 1], aF[1], r4 + 2);
            }
        }
    }

    const int bn = bx * 128;
    const int r0 = bm + wr * 32 + (lid >> 2);
    #pragma unroll
    for (int m2 = 0; m2 < 2; m2++) {
        const int row = r0 + m2 * 16;
        #pragma unroll
        for (int n2 = 0; n2 < 8; n2++) {
            const int col = bn + wc * 64 + n2 * 8 + (lid & 3) * 2;
            const float b0 = __ldg(bias + col);
            const float b1 = __ldg(bias + col + 1);
            float v0 = acc[m2][n2][0] + b0;
            float v1 = acc[m2][n2][1] + b1;
            float v2 = acc[m2][n2][2] + b0;
            float v3 = acc[m2][n2][3] + b1;
            if (act) {
                v0 = elu1(v0); v1 = elu1(v1); v2 = elu1(v2); v3 = elu1(v3);
            }
            *(uint32_t*)(Cv + (size_t)row * EMB + col)       = packh2(v0, v1);
            *(uint32_t*)(Cv + (size_t)(row + 8) * EMB + col) = packh2(v2, v3);
        }
    }
}

// ===========================================================================
// Output-projection GEMM (fp16 in, fp32 out) — same B-via-ldmatrix path.
// ===========================================================================
__global__ __launch_bounds__(256, 2)
void gemm_out_kernel(const __half* __restrict__ Ah,
                     const __half* __restrict__ Wh,
                     const float* __restrict__ bias,
                     float* __restrict__ Cf)
{
    extern __shared__ uint32_t sm[];
    const uint32_t smb = smem_u32(sm);

    const int t   = threadIdx.x;
    const int lid = t & 31;
    const int wid = t >> 5;
    const int wr  = wid >> 1;
    const int wc  = wid & 1;
    const int bx  = blockIdx.x;
    const int bm  = blockIdx.y * 128;

    auto issue = [&](int c, int s) {
        const uint32_t st = smb + (uint32_t)s * (STG_W * 4);
        #pragma unroll
        for (int i = 0; i < 4; i++) {
            const int id  = t + i * 256;
            const int row = id >> 3;
            const int j   = id & 7;
            cp16(st + row * AS_B + j * 16,
                 Ah + (size_t)(bm + row) * EMB + c * 64 + j * 8);
        }
        const uint32_t stB = st + A_STG * 4;
        #pragma unroll
        for (int i = 0; i < 4; i++) {
            const int id  = t + i * 256;
            const int row = id >> 4;
            const int j   = id & 15;
            cp16(stB + row * BS_B + j * 16,
                 Wh + (size_t)(c * 64 + row) * EMB + bx * 128 + j * 8);
        }
        CP_COMMIT();
    };

    float acc[2][8][4];
    #pragma unroll
    for (int i = 0; i < 2; i++)
        #pragma unroll
        for (int j = 0; j < 8; j++)
            #pragma unroll
            for (int k = 0; k < 4; k++)
                acc[i][j][k] = 0.f;

    const int g2 = lid >> 3;
    const int l8 = lid & 7;
    const int b_row = (g2 & 1) * 8 + l8;
    const int b_col = (g2 >> 1) * 8;

    issue(0, 0);
    issue(1, 1);

    for (int c = 0; c < 8; c++) {
        const int s = c % 3;
        if (c >= 6) { CP_WAIT0(); } else { CP_WAIT1(); }
        __syncthreads();
        if (c + 2 < 8) issue(c + 2, (c + 2) % 3);

        const uint32_t stA = smb + (uint32_t)s * (STG_W * 4);
        const uint32_t stB = stA + A_STG * 4;

        #pragma unroll
        for (int ks = 0; ks < 4; ks++) {
            uint32_t aF[2][4];
            #pragma unroll
            for (int m2 = 0; m2 < 2; m2++)
                ldmx4(aF[m2], stA + (wr * 32 + m2 * 16 + (lid & 15)) * AS_B
                               + ks * 32 + (lid >> 4) * 16);
            #pragma unroll
            for (int np = 0; np < 4; np++) {
                uint32_t r4[4];
                ldmx4t(r4, stB + (ks * 16 + b_row) * BS_B
                             + (wc * 64 + np * 16 + b_col) * 2);
                mma16(acc[0][2 * np],     aF[0], r4);
                mma16(acc[0][2 * np + 1], aF[0], r4 + 2);
                mma16(acc[1][2 * np],     aF[1], r4);
                mma16(acc[1][2 * np + 1], aF[1], r4 + 2);
            }
        }
    }

    const int bn = bx * 128;
    const int r0 = bm + wr * 32 + (lid >> 2);
    #pragma unroll
    for (int m2 = 0; m2 < 2; m2++) {
        const int row = r0 + m2 * 16;
        #pragma unroll
        for (int n2 = 0; n2 < 8; n2++) {
            const int col = bn + wc * 64 + n2 * 8 + (lid & 3) * 2;
            const float b0 = __ldg(bias + col);
            const float b1 = __ldg(bias + col + 1);
            float2 o0; o0.x = acc[m2][n2][0] + b0; o0.y = acc[m2][n2][1] + b1;
            float2 o1; o1.x = acc[m2][n2][2] + b0; o1.y = acc[m2][n2][3] + b1;
            *(float2*)(Cf + (size_t)row * EMB + col) = o0;
            *(float2*)(Cf + (size_t)(row + 8) * EMB + col) = o1;
        }
    }
}

// ===========================================================================
// Tensorized KtV + ksum -> packed fp16 output g_KtVh[g][d2][e]  (validated)
// ===========================================================================
#define KTV_KST   9216
#define KTV_VST   11264
#define KTV_STG   (KTV_KST + KTV_VST)
#define KTV_SMEM  (3 * KTV_STG)

__global__ __launch_bounds__(256)
void ktv_mma_kernel(const __half* __restrict__ Kp,
                    const __half* __restrict__ Vp,
                    uint32_t* __restrict__ KtVh)
{
    extern __shared__ uint32_t sm[];
    const uint32_t smb = smem_u32(sm);

    const int g  = blockIdx.x;
    const int bs = g >> 3;
    const int h  = g & 7;
    const size_t rowbase = (size_t)bs * ALEN;
    const int coff = h * HDIM;

    const int t   = threadIdx.x;
    const int lid = t & 31;
    const int wid = t >> 5;
    const int mt  = wid >> 1;
    const int nh  = wid & 1;
    const int ntc = 5 - nh;
    const int n0  = nh * 40;

    if (t < 64) {
        #pragma unroll
        for (int s = 0; s < 3; s++) {
            __half* vb = (__half*)((char*)sm + s * KTV_STG + KTV_KST);
            vb[t * 88 + 64] = __float2half(1.0f);
        }
    }

    auto issue = [&](int c, int s) {
        const uint32_t stK = smb + (uint32_t)s * KTV_STG;
        const uint32_t stV = stK + KTV_KST;
        const int a0 = c * 64;
        #pragma unroll
        for (int i = 0; i < 2; i++) {
            const int id  = t + i * 256;
            const int row = id >> 3;
            const int j   = id & 7;
            const size_t goff = (rowbase + a0 + row) * EMB + coff + j * 8;
            cp16(stK + row * 144 + j * 16, Kp + goff);
            cp16(stV + row * 176 + j * 16, Vp + goff);
        }
        CP_COMMIT();
    };

    float acc[5][4];
    #pragma unroll
    for (int i = 0; i < 5; i++)
        #pragma unroll
        for (int j = 0; j < 4; j++)
            acc[i][j] = 0.f;

    const int g2 = lid >> 3;
    const int l8 = lid & 7;
    const int a_rowA = (g2 >> 1) * 8 + l8;
    const int a_colA = mt * 16 + (g2 & 1) * 8;
    const int a_rowB = (g2 & 1) * 8 + l8;
    const int a_colB = (g2 >> 1) * 8;
    const int a_rowB2 = ((lid >> 3) & 1) * 8 + l8;

    issue(0, 0);
    issue(1, 1);

    for (int c = 0; c < 32; c++) {
        const int s = c % 3;
        if (c >= 30) { CP_WAIT0(); } else { CP_WAIT1(); }
        __syncthreads();
        if (c + 2 < 32) issue(c + 2, (c + 2) % 3);

        const uint32_t stK = smb + (uint32_t)s * KTV_STG;
        const uint32_t stV = stK + KTV_KST;

        #pragma unroll
        for (int ks = 0; ks < 4; ks++) {
            uint32_t aF[4];
            ldmx4t(aF, stK + (ks * 16 + a_rowA) * 144 + a_colA * 2);

            uint32_t bF[5][2];
            {
                uint32_t r4[4];
                ldmx4t(r4, stV + (ks * 16 + a_rowB) * 176 + (n0 + a_colB) * 2);
                bF[0][0] = r4[0]; bF[0][1] = r4[1];
                bF[1][0] = r4[2]; bF[1][1] = r4[3];
                ldmx4t(r4, stV + (ks * 16 + a_rowB) * 176 + (n0 + 16 + a_colB) * 2);
                bF[2][0] = r4[0]; bF[2][1] = r4[1];
                bF[3][0] = r4[2]; bF[3][1] = r4[3];
            }
            if (nh == 0) {
                uint32_t r2[2];
                ldmx2t(r2, stV + (ks * 16 + a_rowB2) * 176 + (n0 + 32) * 2);
                bF[4][0] = r2[0]; bF[4][1] = r2[1];
            }

            #pragma unroll
            for (int nt = 0; nt < 4; nt++)
                mma16(acc[nt], aF, bF[nt]);
            if (nh == 0)
                mma16(acc[4], aF, bF[4]);
        }
    }

    uint32_t* Kout = KtVh + (size_t)g * 2304;
    const int r2 = lid >> 2;
    #pragma unroll
    for (int nt = 0; nt < 5; nt++) {
        if (nt >= ntc) break;
        const int n = n0 + nt * 8;
        #pragma unroll
        for (int c = 0; c < 4; c++) {
            const float v  = acc[nt][c];
            const float vo = __shfl_xor_sync(0xffffffffu, v, 4);
            if ((r2 & 1) == 0) {
                const int d2 = mt * 8 + (r2 >> 1) + 4 * (c >> 1);
                const int e  = n + (lid & 3) * 2 + (c & 1);
                if (e <= 64) Kout[d2 * 72 + e] = packh2(v, vo);
            }
        }
    }
    if (t < 224) Kout[(t / 7) * 72 + 65 + (t % 7)] = 0u;
}

// ===========================================================================
// fp16 tensorized apply — reads PACKED KtVh (plain copy into smem).
// ===========================================================================
#define AQ_B  144
#define SM_S  72
#define APPLY_SMEM ((128 * 36 + 32 * SM_S) * 4)   // 27648 B

__global__ __launch_bounds__(256, 4)
void apply_h_kernel(const __half* __restrict__ Qp,
                    const uint32_t* __restrict__ KtVh,
                    __half* __restrict__ AO)
{
    extern __shared__ uint32_t sm[];
    const uint32_t sQb = smem_u32(sm);
    uint32_t* sM = sm + 128 * 36;

    const int g    = blockIdx.y;
    const int tile = blockIdx.x;
    const int bs   = g >> 3;
    const int h    = g & 7;
    const int t    = threadIdx.x;
    const int lid  = t & 31;
    const int wid  = t >> 5;

    {
        const uint32_t* src = KtVh + (size_t)g * 2304;
        #pragma unroll
        for (int i = t; i < 2304; i += 256) sM[i] = src[i];
    }
    {
        #pragma unroll
        for (int i = 0; i < 4; i++) {
            const int id  = t + i * 256;
            const int row = id >> 3;
            const int j   = id & 7;
            const uint4 v = *(const uint4*)
                (Qp + ((size_t)bs * ALEN + tile * 128 + row) * EMB + h * HDIM + j * 8);
            *(uint4*)((char*)sm + row * AQ_B + j * 16) = v;
        }
    }
    __syncthreads();

    float acc[9][4];
    #pragma unroll
    for (int i = 0; i < 9; i++)
        #pragma unroll
        for (int j = 0; j < 4; j++)
            acc[i][j] = 0.f;

    #pragma unroll
    for (int ks = 0; ks < 4; ks++) {
        uint32_t aF[4];
        ldmx4(aF, sQb + (wid * 16 + (lid & 15)) * AQ_B + ks * 32 + (lid >> 4) * 16);
        #pragma unroll
        for (int n2 = 0; n2 < 9; n2++) {
            uint32_t bF[2];
            const int n = n2 * 8 + (lid >> 2);
            bF[0] = sM[(ks * 8 + (lid & 3)) * SM_S + n];
            bF[1] = sM[(ks * 8 + 4 + (lid & 3)) * SM_S + n];
            mma16(acc[n2], aF, bF);
        }
    }

    const float den0 = __shfl_sync(0xffffffffu, acc[8][0], lid & ~3);
    const float den1 = __shfl_sync(0xffffffffu, acc[8][2], lid & ~3);
    const float z0 = 1.f / (den0 + EPS_F);
    const float z1 = 1.f / (den1 + EPS_F);

    const int arow = tile * 128 + wid * 16 + (lid >> 2);
    const size_t base = ((size_t)bs * ALEN + arow) * EMB + h * HDIM;
    #pragma unroll
    for (int n2 = 0; n2 < 8; n2++) {
        const int col = n2 * 8 + (lid & 3) * 2;
        *(uint32_t*)(AO + base + col) = packh2(z0 * acc[n2][0], z0 * acc[n2][1]);
        *(uint32_t*)(AO + base + (size_t)8 * EMB + col) =
            packh2(z1 * acc[n2][2], z1 * acc[n2][3]);
    }
}

// ---------------------------------------------------------------------------
extern "C" void kernel_launch(void* const* d_in, const int* in_sizes, int n_in,
                              void* d_out, int out_size)
{
    const float* input_q  = (const float*)d_in[0];
    const float* input_kv = (const float*)d_in[1];
    const float* Wq = (const float*)d_in[2];
    const float* bq = (const float*)d_in[3];
    const float* Wk = (const float*)d_in[4];
    const float* bk = (const float*)d_in[5];
    const float* Wv = (const float*)d_in[6];
    const float* bv = (const float*)d_in[7];
    const float* Wo = (const float*)d_in[8];
    const float* bo = (const float*)d_in[9];
    float* out = (float*)d_out;

    void *p0, *p1, *p2, *p3, *p4, *p5, *p8, *p10;
    cudaGetSymbolAddress(&p0,  g_iqh);
    cudaGetSymbolAddress(&p1,  g_ikh);
    cudaGetSymbolAddress(&p2,  g_Qh);
    cudaGetSymbolAddress(&p3,  g_Kh);
    cudaGetSymbolAddress(&p4,  g_Vh);
    cudaGetSymbolAddress(&p5,  g_AOh);
    cudaGetSymbolAddress(&p8,  g_KtVh);
    cudaGetSymbolAddress(&p10, g_Whf);
    __half*   iqh  = (__half*)p0;
    __half*   ikh  = (__half*)p1;
    __half*   Qh   = (__half*)p2;
    __half*   Kh   = (__half*)p3;
    __half*   Vh   = (__half*)p4;
    __half*   AOh  = (__half*)p5;
    uint32_t* KtVh = (uint32_t*)p8;
    __half*   Whf  = (__half*)p10;

    cudaFuncSetAttribute((const void*)gemm_qkv_kernel,
                         cudaFuncAttributeMaxDynamicSharedMemorySize, GEMM_SMEM);
    cudaFuncSetAttribute((const void*)gemm_out_kernel,
                         cudaFuncAttributeMaxDynamicSharedMemorySize, GEMM_SMEM);
    cudaFuncSetAttribute((const void*)ktv_mma_kernel,
                         cudaFuncAttributeMaxDynamicSharedMemorySize, KTV_SMEM);
    cudaFuncSetAttribute((const void*)apply_h_kernel,
                         cudaFuncAttributeMaxDynamicSharedMemorySize, APPLY_SMEM);

    const size_t WSZ = (size_t)EMB * EMB;

    // prep
    wprep4_kernel<<<1024, 256>>>(Wq, Wk, Wv, Wo, Whf);
    aprep2_kernel<<<2 * APREP_BLKS_PER, 256>>>(input_q, iqh, input_kv, ikh);

    // Merged Q+K+V projection (grid.x = 12)
    gemm_qkv_kernel<<<dim3(12, M_TOK / 128), 256, GEMM_SMEM>>>(
        iqh, ikh, Whf, bq, bk, bv, Qh, Kh, Vh);

    // KtV + ksum (packed fp16 output)
    ktv_mma_kernel<<<NGROUP, 256, KTV_SMEM>>>(Kh, Vh, KtVh);

    // apply (reads packed KtVh)
    apply_h_kernel<<<dim3(ALEN / 128, NGROUP), 256, APPLY_SMEM>>>(Qh, KtVh, AOh);

    // Output projection (fp32 out)
    gemm_out_kernel<<<dim3(4, M_TOK / 128), 256, GEMM_SMEM>>>(
        AOh, Whf + 3 * WSZ, bo, out);
}

// round 16
// speedup vs baseline: 1.0422x; 1.0422x over previous
#include <cuda_runtime.h>
#include <cuda_fp16.h>
#include <cstdint>

// Problem constants
#define M_TOK   131072      // b*s*a = 2*32*2048
#define EMB     512
#define NHEAD   8
#define HDIM    64
#define NGROUP  512         // b*s*h = 64*8
#define ALEN    2048
#define EPS_F   1e-6f

// Scratch (device globals: allocation-free per harness rules)
__device__ __half   g_iqh[(size_t)M_TOK * EMB];
__device__ __half   g_ikh[(size_t)M_TOK * EMB];
__device__ __half   g_Qh [(size_t)M_TOK * EMB];
__device__ __half   g_Kh [(size_t)M_TOK * EMB];
__device__ __half   g_Vh [(size_t)M_TOK * EMB];
__device__ __half   g_AOh[(size_t)M_TOK * EMB];
__device__ uint32_t g_KtVh[(size_t)NGROUP * 2304];  // packed fp16 [g][d2(32)][e(72)]
__device__ uint32_t g_Wf [4 * (size_t)131072];      // fragment-packed fp16 weights

// ---------------------------------------------------------------------------
__device__ __forceinline__ void mma16(float* d, const uint32_t* a, const uint32_t* b) {
    asm volatile(
        "mma.sync.aligned.m16n8k16.row.col.f32.f16.f16.f32 "
        "{%0,%1,%2,%3},{%4,%5,%6,%7},{%8,%9},{%0,%1,%2,%3};"
        : "+f"(d[0]), "+f"(d[1]), "+f"(d[2]), "+f"(d[3])
        : "r"(a[0]), "r"(a[1]), "r"(a[2]), "r"(a[3]),
          "r"(b[0]), "r"(b[1]));
}

__device__ __forceinline__ void ldmx4(uint32_t* r, uint32_t addr) {
    asm volatile("ldmatrix.sync.aligned.m8n8.x4.shared.b16 {%0,%1,%2,%3}, [%4];"
                 : "=r"(r[0]), "=r"(r[1]), "=r"(r[2]), "=r"(r[3]) : "r"(addr));
}
__device__ __forceinline__ void ldmx4t(uint32_t* r, uint32_t addr) {
    asm volatile("ldmatrix.sync.aligned.m8n8.x4.trans.shared.b16 {%0,%1,%2,%3}, [%4];"
                 : "=r"(r[0]), "=r"(r[1]), "=r"(r[2]), "=r"(r[3]) : "r"(addr));
}
__device__ __forceinline__ void ldmx2t(uint32_t* r, uint32_t addr) {
    asm volatile("ldmatrix.sync.aligned.m8n8.x2.trans.shared.b16 {%0,%1}, [%2];"
                 : "=r"(r[0]), "=r"(r[1]) : "r"(addr));
}

__device__ __forceinline__ uint32_t smem_u32(const void* p) {
    uint32_t a;
    asm("{ .reg .u64 t; cvta.to.shared.u64 t, %1; cvt.u32.u64 %0, t; }"
        : "=r"(a) : "l"(p));
    return a;
}

__device__ __forceinline__ void cp16(uint32_t dst, const void* src) {
    asm volatile("cp.async.cg.shared.global [%0], [%1], 16;"
                 :: "r"(dst), "l"(src) : "memory");
}
#define CP_COMMIT() asm volatile("cp.async.commit_group;" ::: "memory")
#define CP_WAIT1()  asm volatile("cp.async.wait_group 1;" ::: "memory")
#define CP_WAIT0()  asm volatile("cp.async.wait_group 0;" ::: "memory")

__device__ __forceinline__ uint32_t packh2(float a, float b) {
    __half2 h = __floats2half2_rn(a, b);
    return *(uint32_t*)&h;
}
__device__ __forceinline__ float elu1(float v) {
    return v > 0.f ? v + 1.f : expf(v);
}

// Fragment mapping (m16n8k16, validated):
//   A: lane l, reg rg: pairs A[(l>>2)+8*(rg&1)][(l&3)*2 + 8*(rg>>1) + {0,1}]
//   B: lane l, reg rg: pairs B[k=(l&3)*2+8*rg+{0,1}][n=(l>>2)]
//   C: lane l, reg c:  row=(l>>2)+8*(c>>1), col=(l&3)*2+(c&1)

// ===========================================================================
// Prep: fp32 -> fp16 for both inputs in ONE launch
// ===========================================================================
#define APREP_BLKS_PER 32768
__global__ __launch_bounds__(256)
void aprep2_kernel(const float* __restrict__ s0, __half* __restrict__ d0,
                   const float* __restrict__ s1, __half* __restrict__ d1)
{
    const int b = blockIdx.x;
    const float* src = (b < APREP_BLKS_PER) ? s0 : s1;
    __half*      dst = (b < APREP_BLKS_PER) ? d0 : d1;
    const size_t i = ((size_t)(b & (APREP_BLKS_PER - 1)) * 256 + threadIdx.x) * 8;
    const float4 a = *(const float4*)(src + i);
    const float4 c = *(const float4*)(src + i + 4);
    __half2 h[4];
    h[0] = __floats2half2_rn(a.x, a.y);
    h[1] = __floats2half2_rn(a.z, a.w);
    h[2] = __floats2half2_rn(c.x, c.y);
    h[3] = __floats2half2_rn(c.z, c.w);
    *(uint4*)(dst + i) = *(uint4*)h;
}

// ===========================================================================
// Weight prep — fragment-packed fp16, all 4 weights in ONE launch (R14)
// ===========================================================================
__global__ __launch_bounds__(256)
void wprep4_kernel(const float* __restrict__ W0, const float* __restrict__ W1,
                   const float* __restrict__ W2, const float* __restrict__ W3,
                   uint32_t* __restrict__ Wf)
{
    const int w   = blockIdx.x >> 9;
    const float* W = (w == 0) ? W0 : (w == 1) ? W1 : (w == 2) ? W2 : W3;
    const int o   = (blockIdx.x & 511) * 256 + threadIdx.x;
    const int rg  = o & 1;
    const int l   = (o >> 1) & 31;
    const int ntg = (o >> 6) & 63;
    const int ks  = (o >> 12) & 3;
    const int c   = o >> 14;
    const int k0  = c * 64 + ks * 16 + (l & 3) * 2 + 8 * rg;
    const int n   = ntg * 8 + (l >> 2);
    Wf[(size_t)w * 131072 + o] =
        packh2(W[(size_t)k0 * EMB + n], W[(size_t)(k0 + 1) * EMB + n]);
}

// ===========================================================================
// Shared GEMM config (R10/R14-validated: 3-stage, 32x64 warp tile)
// ===========================================================================
#define AS_B    144
#define A_STG   (128 * 36)
#define B_STG   4096
#define STG_W   (A_STG + B_STG)
#define GEMM_SMEM (3 * STG_W * 4)     // 104448 B; 2 CTAs fit

// ===========================================================================
// Q/K/V projection GEMM with weight offset (for split-stream launches).
//   w = (bx>>2) + wofs : 0 -> Q (A=iq, bq, Qo, elu+1)
//                        1 -> K (A=ik, bk, Ko, elu+1)
//                        2 -> V (A=ik, bv, Vo, identity)
// ===========================================================================
__global__ __launch_bounds__(256, 2)
void gemm_qkv_kernel(const __half* __restrict__ iq,
                     const __half* __restrict__ ik,
                     const uint32_t* __restrict__ WfBase,
                     const float* __restrict__ bq,
                     const float* __restrict__ bk,
                     const float* __restrict__ bv,
                     __half* __restrict__ Qo,
                     __half* __restrict__ Ko,
                     __half* __restrict__ Vo,
                     int wofs)
{
    extern __shared__ uint32_t sm[];
    const uint32_t smb = smem_u32(sm);

    const int t   = threadIdx.x;
    const int lid = t & 31;
    const int wid = t >> 5;
    const int wr  = wid >> 1;
    const int wc  = wid & 1;
    const int w   = (blockIdx.x >> 2) + wofs;   // 0..2
    const int bx  = blockIdx.x & 3;
    const int bm  = blockIdx.y * 128;

    const __half* Ah   = (w == 0) ? iq : ik;
    const uint32_t* Wf = WfBase + (size_t)w * 131072;
    const float* bias  = (w == 0) ? bq : (w == 1) ? bk : bv;
    __half* Cv         = (w == 0) ? Qo : (w == 1) ? Ko : Vo;
    const int act      = (w < 2);

    const uint4* W4 = (const uint4*)Wf;

    auto issue = [&](int c, int s) {
        const uint32_t st = smb + (uint32_t)s * (STG_W * 4);
        #pragma unroll
        for (int i = 0; i < 4; i++) {
            const int id  = t + i * 256;
            const int row = id >> 3;
            const int j   = id & 7;
            cp16(st + row * AS_B + j * 16,
                 Ah + (size_t)(bm + row) * EMB + c * 64 + j * 8);
        }
        #pragma unroll
        for (int i = 0; i < 4; i++) {
            const int id   = t + i * 256;
            const int ks   = id >> 8;
            const int rest = id & 255;
            cp16(st + (A_STG + ks * 1024) * 4 + rest * 16,
                 W4 + (size_t)((c * 4 + ks) * 64 + bx * 16) * 16 + rest);
        }
        CP_COMMIT();
    };

    float acc[2][8][4];
    #pragma unroll
    for (int i = 0; i < 2; i++)
        #pragma unroll
        for (int j = 0; j < 8; j++)
            #pragma unroll
            for (int k = 0; k < 4; k++)
                acc[i][j][k] = 0.f;

    issue(0, 0);
    issue(1, 1);

    for (int c = 0; c < 8; c++) {
        const int s = c % 3;
        if (c >= 6) { CP_WAIT0(); } else { CP_WAIT1(); }
        __syncthreads();
        if (c + 2 < 8) issue(c + 2, (c + 2) % 3);

        const uint32_t stA = smb + (uint32_t)s * (STG_W * 4);
        const uint32_t* Bb = sm + s * STG_W + A_STG;

        #pragma unroll
        for (int ks = 0; ks < 4; ks++) {
            uint32_t aF[2][4];
            #pragma unroll
            for (int m2 = 0; m2 < 2; m2++)
                ldmx4(aF[m2], stA + (wr * 32 + m2 * 16 + (lid & 15)) * AS_B
                               + ks * 32 + (lid >> 4) * 16);
            uint32_t bF[8][2];
            #pragma unroll
            for (int n2 = 0; n2 < 8; n2++) {
                const uint2 v = *(const uint2*)
                    &Bb[ks * 1024 + (wc * 8 + n2) * 64 + lid * 2];
                bF[n2][0] = v.x; bF[n2][1] = v.y;
            }
            #pragma unroll
            for (int m2 = 0; m2 < 2; m2++)
                #pragma unroll
                for (int n2 = 0; n2 < 8; n2++)
                    mma16(acc[m2][n2], aF[m2], bF[n2]);
        }
    }

    const int bn = bx * 128;
    const int r0 = bm + wr * 32 + (lid >> 2);
    #pragma unroll
    for (int m2 = 0; m2 < 2; m2++) {
        const int row = r0 + m2 * 16;
        #pragma unroll
        for (int n2 = 0; n2 < 8; n2++) {
            const int col = bn + wc * 64 + n2 * 8 + (lid & 3) * 2;
            const float b0 = __ldg(bias + col);
            const float b1 = __ldg(bias + col + 1);
            float v0 = acc[m2][n2][0] + b0;
            float v1 = acc[m2][n2][1] + b1;
            float v2 = acc[m2][n2][2] + b0;
            float v3 = acc[m2][n2][3] + b1;
            if (act) {
                v0 = elu1(v0); v1 = elu1(v1); v2 = elu1(v2); v3 = elu1(v3);
            }
            *(uint32_t*)(Cv + (size_t)row * EMB + col)       = packh2(v0, v1);
            *(uint32_t*)(Cv + (size_t)(row + 8) * EMB + col) = packh2(v2, v3);
        }
    }
}

// ===========================================================================
// Output-projection GEMM (fp16 in, fp32 out) — R14 validated kernel.
// ===========================================================================
__global__ __launch_bounds__(256, 2)
void gemm_out_kernel(const __half* __restrict__ Ah,
                     const uint32_t* __restrict__ Wf,
                     const float* __restrict__ bias,
                     float* __restrict__ Cf)
{
    extern __shared__ uint32_t sm[];
    const uint32_t smb = smem_u32(sm);

    const int t   = threadIdx.x;
    const int lid = t & 31;
    const int wid = t >> 5;
    const int wr  = wid >> 1;
    const int wc  = wid & 1;
    const int bx  = blockIdx.x;
    const int bm  = blockIdx.y * 128;

    const uint4* W4 = (const uint4*)Wf;

    auto issue = [&](int c, int s) {
        const uint32_t st = smb + (uint32_t)s * (STG_W * 4);
        #pragma unroll
        for (int i = 0; i < 4; i++) {
            const int id  = t + i * 256;
            const int row = id >> 3;
            const int j   = id & 7;
            cp16(st + row * AS_B + j * 16,
                 Ah + (size_t)(bm + row) * EMB + c * 64 + j * 8);
        }
        #pragma unroll
        for (int i = 0; i < 4; i++) {
            const int id   = t + i * 256;
            const int ks   = id >> 8;
            const int rest = id & 255;
            cp16(st + (A_STG + ks * 1024) * 4 + rest * 16,
                 W4 + (size_t)((c * 4 + ks) * 64 + bx * 16) * 16 + rest);
        }
        CP_COMMIT();
    };

    float acc[2][8][4];
    #pragma unroll
    for (int i = 0; i < 2; i++)
        #pragma unroll
        for (int j = 0; j < 8; j++)
            #pragma unroll
            for (int k = 0; k < 4; k++)
                acc[i][j][k] = 0.f;

    issue(0, 0);
    issue(1, 1);

    for (int c = 0; c < 8; c++) {
        const int s = c % 3;
        if (c >= 6) { CP_WAIT0(); } else { CP_WAIT1(); }
        __syncthreads();
        if (c + 2 < 8) issue(c + 2, (c + 2) % 3);

        const uint32_t stA = smb + (uint32_t)s * (STG_W * 4);
        const uint32_t* Bb = sm + s * STG_W + A_STG;

        #pragma unroll
        for (int ks = 0; ks < 4; ks++) {
            uint32_t aF[2][4];
            #pragma unroll
            for (int m2 = 0; m2 < 2; m2++)
                ldmx4(aF[m2], stA + (wr * 32 + m2 * 16 + (lid & 15)) * AS_B
                               + ks * 32 + (lid >> 4) * 16);
            uint32_t bF[8][2];
            #pragma unroll
            for (int n2 = 0; n2 < 8; n2++) {
                const uint2 v = *(const uint2*)
                    &Bb[ks * 1024 + (wc * 8 + n2) * 64 + lid * 2];
                bF[n2][0] = v.x; bF[n2][1] = v.y;
            }
            #pragma unroll
            for (int m2 = 0; m2 < 2; m2++)
                #pragma unroll
                for (int n2 = 0; n2 < 8; n2++)
                    mma16(acc[m2][n2], aF[m2], bF[n2]);
        }
    }

    const int bn = bx * 128;
    const int r0 = bm + wr * 32 + (lid >> 2);
    #pragma unroll
    for (int m2 = 0; m2 < 2; m2++) {
        const int row = r0 + m2 * 16;
        #pragma unroll
        for (int n2 = 0; n2 < 8; n2++) {
            const int col = bn + wc * 64 + n2 * 8 + (lid & 3) * 2;
            const float b0 = __ldg(bias + col);
            const float b1 = __ldg(bias + col + 1);
            float2 o0; o0.x = acc[m2][n2][0] + b0; o0.y = acc[m2][n2][1] + b1;
            float2 o1; o1.x = acc[m2][n2][2] + b0; o1.y = acc[m2][n2][3] + b1;
            *(float2*)(Cf + (size_t)row * EMB + col) = o0;
            *(float2*)(Cf + (size_t)(row + 8) * EMB + col) = o1;
        }
    }
}

// ===========================================================================
// Tensorized KtV + ksum -> packed fp16 output g_KtVh[g][d2][e]  (validated)
// ===========================================================================
#define KTV_KST   9216
#define KTV_VST   11264
#define KTV_STG   (KTV_KST + KTV_VST)
#define KTV_SMEM  (3 * KTV_STG)

__global__ __launch_bounds__(256)
void ktv_mma_kernel(const __half* __restrict__ Kp,
                    const __half* __restrict__ Vp,
                    uint32_t* __restrict__ KtVh)
{
    extern __shared__ uint32_t sm[];
    const uint32_t smb = smem_u32(sm);

    const int g  = blockIdx.x;
    const int bs = g >> 3;
    const int h  = g & 7;
    const size_t rowbase = (size_t)bs * ALEN;
    const int coff = h * HDIM;

    const int t   = threadIdx.x;
    const int lid = t & 31;
    const int wid = t >> 5;
    const int mt  = wid >> 1;
    const int nh  = wid & 1;
    const int ntc = 5 - nh;
    const int n0  = nh * 40;

    if (t < 64) {
        #pragma unroll
        for (int s = 0; s < 3; s++) {
            __half* vb = (__half*)((char*)sm + s * KTV_STG + KTV_KST);
            vb[t * 88 + 64] = __float2half(1.0f);
        }
    }

    auto issue = [&](int c, int s) {
        const uint32_t stK = smb + (uint32_t)s * KTV_STG;
        const uint32_t stV = stK + KTV_KST;
        const int a0 = c * 64;
        #pragma unroll
        for (int i = 0; i < 2; i++) {
            const int id  = t + i * 256;
            const int row = id >> 3;
            const int j   = id & 7;
            const size_t goff = (rowbase + a0 + row) * EMB + coff + j * 8;
            cp16(stK + row * 144 + j * 16, Kp + goff);
            cp16(stV + row * 176 + j * 16, Vp + goff);
        }
        CP_COMMIT();
    };

    float acc[5][4];
    #pragma unroll
    for (int i = 0; i < 5; i++)
        #pragma unroll
        for (int j = 0; j < 4; j++)
            acc[i][j] = 0.f;

    const int g2 = lid >> 3;
    const int l8 = lid & 7;
    const int a_rowA = (g2 >> 1) * 8 + l8;
    const int a_colA = mt * 16 + (g2 & 1) * 8;
    const int a_rowB = (g2 & 1) * 8 + l8;
    const int a_colB = (g2 >> 1) * 8;
    const int a_rowB2 = ((lid >> 3) & 1) * 8 + l8;

    issue(0, 0);
    issue(1, 1);

    for (int c = 0; c < 32; c++) {
        const int s = c % 3;
        if (c >= 30) { CP_WAIT0(); } else { CP_WAIT1(); }
        __syncthreads();
        if (c + 2 < 32) issue(c + 2, (c + 2) % 3);

        const uint32_t stK = smb + (uint32_t)s * KTV_STG;
        const uint32_t stV = stK + KTV_KST;

        #pragma unroll
        for (int ks = 0; ks < 4; ks++) {
            uint32_t aF[4];
            ldmx4t(aF, stK + (ks * 16 + a_rowA) * 144 + a_colA * 2);

            uint32_t bF[5][2];
            {
                uint32_t r4[4];
                ldmx4t(r4, stV + (ks * 16 + a_rowB) * 176 + (n0 + a_colB) * 2);
                bF[0][0] = r4[0]; bF[0][1] = r4[1];
                bF[1][0] = r4[2]; bF[1][1] = r4[3];
                ldmx4t(r4, stV + (ks * 16 + a_rowB) * 176 + (n0 + 16 + a_colB) * 2);
                bF[2][0] = r4[0]; bF[2][1] = r4[1];
                bF[3][0] = r4[2]; bF[3][1] = r4[3];
            }
            if (nh == 0) {
                uint32_t r2[2];
                ldmx2t(r2, stV + (ks * 16 + a_rowB2) * 176 + (n0 + 32) * 2);
                bF[4][0] = r2[0]; bF[4][1] = r2[1];
            }

            #pragma unroll
            for (int nt = 0; nt < 4; nt++)
                mma16(acc[nt], aF, bF[nt]);
            if (nh == 0)
                mma16(acc[4], aF, bF[4]);
        }
    }

    uint32_t* Kout = KtVh + (size_t)g * 2304;
    const int r2 = lid >> 2;
    #pragma unroll
    for (int nt = 0; nt < 5; nt++) {
        if (nt >= ntc) break;
        const int n = n0 + nt * 8;
        #pragma unroll
        for (int c = 0; c < 4; c++) {
            const float v  = acc[nt][c];
            const float vo = __shfl_xor_sync(0xffffffffu, v, 4);
            if ((r2 & 1) == 0) {
                const int d2 = mt * 8 + (r2 >> 1) + 4 * (c >> 1);
                const int e  = n + (lid & 3) * 2 + (c & 1);
                if (e <= 64) Kout[d2 * 72 + e] = packh2(v, vo);
            }
        }
    }
    if (t < 224) Kout[(t / 7) * 72 + 65 + (t % 7)] = 0u;
}

// ===========================================================================
// fp16 tensorized apply — reads PACKED KtVh (plain copy into smem).
// ===========================================================================
#define AQ_B  144
#define SM_S  72
#define APPLY_SMEM ((128 * 36 + 32 * SM_S) * 4)   // 27648 B

__global__ __launch_bounds__(256, 4)
void apply_h_kernel(const __half* __restrict__ Qp,
                    const uint32_t* __restrict__ KtVh,
                    __half* __restrict__ AO)
{
    extern __shared__ uint32_t sm[];
    const uint32_t sQb = smem_u32(sm);
    uint32_t* sM = sm + 128 * 36;

    const int g    = blockIdx.y;
    const int tile = blockIdx.x;
    const int bs   = g >> 3;
    const int h    = g & 7;
    const int t    = threadIdx.x;
    const int lid  = t & 31;
    const int wid  = t >> 5;

    {
        const uint32_t* src = KtVh + (size_t)g * 2304;
        #pragma unroll
        for (int i = t; i < 2304; i += 256) sM[i] = src[i];
    }
    {
        #pragma unroll
        for (int i = 0; i < 4; i++) {
            const int id  = t + i * 256;
            const int row = id >> 3;
            const int j   = id & 7;
            const uint4 v = *(const uint4*)
                (Qp + ((size_t)bs * ALEN + tile * 128 + row) * EMB + h * HDIM + j * 8);
            *(uint4*)((char*)sm + row * AQ_B + j * 16) = v;
        }
    }
    __syncthreads();

    float acc[9][4];
    #pragma unroll
    for (int i = 0; i < 9; i++)
        #pragma unroll
        for (int j = 0; j < 4; j++)
            acc[i][j] = 0.f;

    #pragma unroll
    for (int ks = 0; ks < 4; ks++) {
        uint32_t aF[4];
        ldmx4(aF, sQb + (wid * 16 + (lid & 15)) * AQ_B + ks * 32 + (lid >> 4) * 16);
        #pragma unroll
        for (int n2 = 0; n2 < 9; n2++) {
            uint32_t bF[2];
            const int n = n2 * 8 + (lid >> 2);
            bF[0] = sM[(ks * 8 + (lid & 3)) * SM_S + n];
            bF[1] = sM[(ks * 8 + 4 + (lid & 3)) * SM_S + n];
            mma16(acc[n2], aF, bF);
        }
    }

    const float den0 = __shfl_sync(0xffffffffu, acc[8][0], lid & ~3);
    const float den1 = __shfl_sync(0xffffffffu, acc[8][2], lid & ~3);
    const float z0 = 1.f / (den0 + EPS_F);
    const float z1 = 1.f / (den1 + EPS_F);

    const int arow = tile * 128 + wid * 16 + (lid >> 2);
    const size_t base = ((size_t)bs * ALEN + arow) * EMB + h * HDIM;
    #pragma unroll
    for (int n2 = 0; n2 < 8; n2++) {
        const int col = n2 * 8 + (lid & 3) * 2;
        *(uint32_t*)(AO + base + col) = packh2(z0 * acc[n2][0], z0 * acc[n2][1]);
        *(uint32_t*)(AO + base + (size_t)8 * EMB + col) =
            packh2(z1 * acc[n2][2], z1 * acc[n2][3]);
    }
}

// ---------------------------------------------------------------------------
extern "C" void kernel_launch(void* const* d_in, const int* in_sizes, int n_in,
                              void* d_out, int out_size)
{
    const float* input_q  = (const float*)d_in[0];
    const float* input_kv = (const float*)d_in[1];
    const float* Wq = (const float*)d_in[2];
    const float* bq = (const float*)d_in[3];
    const float* Wk = (const float*)d_in[4];
    const float* bk = (const float*)d_in[5];
    const float* Wv = (const float*)d_in[6];
    const float* bv = (const float*)d_in[7];
    const float* Wo = (const float*)d_in[8];
    const float* bo = (const float*)d_in[9];
    float* out = (float*)d_out;

    void *p0, *p1, *p2, *p3, *p4, *p5, *p8, *p10;
    cudaGetSymbolAddress(&p0,  g_iqh);
    cudaGetSymbolAddress(&p1,  g_ikh);
    cudaGetSymbolAddress(&p2,  g_Qh);
    cudaGetSymbolAddress(&p3,  g_Kh);
    cudaGetSymbolAddress(&p4,  g_Vh);
    cudaGetSymbolAddress(&p5,  g_AOh);
    cudaGetSymbolAddress(&p8,  g_KtVh);
    cudaGetSymbolAddress(&p10, g_Wf);
    __half*   iqh  = (__half*)p0;
    __half*   ikh  = (__half*)p1;
    __half*   Qh   = (__half*)p2;
    __half*   Kh   = (__half*)p3;
    __half*   Vh   = (__half*)p4;
    __half*   AOh  = (__half*)p5;
    uint32_t* KtVh = (uint32_t*)p8;
    uint32_t* Wf   = (uint32_t*)p10;

    cudaFuncSetAttribute((const void*)gemm_qkv_kernel,
                         cudaFuncAttributeMaxDynamicSharedMemorySize, GEMM_SMEM);
    cudaFuncSetAttribute((const void*)gemm_out_kernel,
                         cudaFuncAttributeMaxDynamicSharedMemorySize, GEMM_SMEM);
    cudaFuncSetAttribute((const void*)ktv_mma_kernel,
                         cudaFuncAttributeMaxDynamicSharedMemorySize, KTV_SMEM);
    cudaFuncSetAttribute((const void*)apply_h_kernel,
                         cudaFuncAttributeMaxDynamicSharedMemorySize, APPLY_SMEM);

    const size_t WSZ = 131072;

    // Side stream + events (non-blocking to avoid legacy-stream implicit sync;
    // created fresh per call — no device memory involved).
    cudaStream_t s2;
    cudaStreamCreateWithFlags(&s2, cudaStreamNonBlocking);
    cudaEvent_t eP, eQ;
    cudaEventCreateWithFlags(&eP, cudaEventDisableTiming);
    cudaEventCreateWithFlags(&eQ, cudaEventDisableTiming);

    // default stream: preps
    wprep4_kernel<<<2048, 256>>>(Wq, Wk, Wv, Wo, Wf);
    aprep2_kernel<<<2 * APREP_BLKS_PER, 256>>>(input_q, iqh, input_kv, ikh);
    cudaEventRecord(eP, 0);

    // side stream: Q projection (depends only on preps)
    cudaStreamWaitEvent(s2, eP, 0);
    gemm_qkv_kernel<<<dim3(4, M_TOK / 128), 256, GEMM_SMEM, s2>>>(
        iqh, ikh, Wf, bq, bk, bv, Qh, Kh, Vh, /*wofs=*/0);
    cudaEventRecord(eQ, s2);

    // default stream: K+V projection, then ktv (overlaps Q on s2)
    gemm_qkv_kernel<<<dim3(8, M_TOK / 128), 256, GEMM_SMEM>>>(
        iqh, ikh, Wf, bq, bk, bv, Qh, Kh, Vh, /*wofs=*/1);
    ktv_mma_kernel<<<NGROUP, 256, KTV_SMEM>>>(Kh, Vh, KtVh);

    // join: apply needs Q and KtVh
    cudaStreamWaitEvent(0, eQ, 0);
    apply_h_kernel<<<dim3(ALEN / 128, NGROUP), 256, APPLY_SMEM>>>(Qh, KtVh, AOh);

    // Output projection (fp32 out)
    gemm_out_kernel<<<dim3(4, M_TOK / 128), 256, GEMM_SMEM>>>(
        AOh, Wf + 3 * WSZ, bo, out);
}

// round 17
// speedup vs baseline: 1.0498x; 1.0073x over previous
#include <cuda_runtime.h>
#include <cuda_fp16.h>
#include <cstdint>

// Problem constants
#define M_TOK   131072      // b*s*a = 2*32*2048
#define EMB     512
#define NHEAD   8
#define HDIM    64
#define NGROUP  512         // b*s*h = 64*8
#define ALEN    2048
#define EPS_F   1e-6f

// Scratch (device globals: allocation-free per harness rules)
__device__ __half   g_iqh[(size_t)M_TOK * EMB];
__device__ __half   g_ikh[(size_t)M_TOK * EMB];
__device__ __half   g_Qh [(size_t)M_TOK * EMB];
__device__ __half   g_Kh [(size_t)M_TOK * EMB];
__device__ __half   g_Vh [(size_t)M_TOK * EMB];
__device__ __half   g_AOh[(size_t)M_TOK * EMB];
__device__ uint32_t g_KtVh[(size_t)NGROUP * 2304];  // packed fp16 [g][d2(32)][e(72)]
__device__ uint32_t g_Wf [4 * (size_t)131072];      // fragment-packed fp16 weights

// ---------------------------------------------------------------------------
__device__ __forceinline__ void mma16(float* d, const uint32_t* a, const uint32_t* b) {
    asm volatile(
        "mma.sync.aligned.m16n8k16.row.col.f32.f16.f16.f32 "
        "{%0,%1,%2,%3},{%4,%5,%6,%7},{%8,%9},{%0,%1,%2,%3};"
        : "+f"(d[0]), "+f"(d[1]), "+f"(d[2]), "+f"(d[3])
        : "r"(a[0]), "r"(a[1]), "r"(a[2]), "r"(a[3]),
          "r"(b[0]), "r"(b[1]));
}

__device__ __forceinline__ void ldmx4(uint32_t* r, uint32_t addr) {
    asm volatile("ldmatrix.sync.aligned.m8n8.x4.shared.b16 {%0,%1,%2,%3}, [%4];"
                 : "=r"(r[0]), "=r"(r[1]), "=r"(r[2]), "=r"(r[3]) : "r"(addr));
}
__device__ __forceinline__ void ldmx4t(uint32_t* r, uint32_t addr) {
    asm volatile("ldmatrix.sync.aligned.m8n8.x4.trans.shared.b16 {%0,%1,%2,%3}, [%4];"
                 : "=r"(r[0]), "=r"(r[1]), "=r"(r[2]), "=r"(r[3]) : "r"(addr));
}
__device__ __forceinline__ void ldmx2t(uint32_t* r, uint32_t addr) {
    asm volatile("ldmatrix.sync.aligned.m8n8.x2.trans.shared.b16 {%0,%1}, [%2];"
                 : "=r"(r[0]), "=r"(r[1]) : "r"(addr));
}

__device__ __forceinline__ uint32_t smem_u32(const void* p) {
    uint32_t a;
    asm("{ .reg .u64 t; cvta.to.shared.u64 t, %1; cvt.u32.u64 %0, t; }"
        : "=r"(a) : "l"(p));
    return a;
}

__device__ __forceinline__ void cp16(uint32_t dst, const void* src) {
    asm volatile("cp.async.cg.shared.global [%0], [%1], 16;"
                 :: "r"(dst), "l"(src) : "memory");
}
#define CP_COMMIT() asm volatile("cp.async.commit_group;" ::: "memory")
#define CP_WAIT1()  asm volatile("cp.async.wait_group 1;" ::: "memory")
#define CP_WAIT0()  asm volatile("cp.async.wait_group 0;" ::: "memory")

__device__ __forceinline__ uint32_t packh2(float a, float b) {
    __half2 h = __floats2half2_rn(a, b);
    return *(uint32_t*)&h;
}
__device__ __forceinline__ float elu1(float v) {
    return v > 0.f ? v + 1.f : expf(v);
}

// Fragment mapping (m16n8k16, validated):
//   A: lane l, reg rg: pairs A[(l>>2)+8*(rg&1)][(l&3)*2 + 8*(rg>>1) + {0,1}]
//   B: lane l, reg rg: pairs B[k=(l&3)*2+8*rg+{0,1}][n=(l>>2)]
//   C: lane l, reg c:  row=(l>>2)+8*(c>>1), col=(l&3)*2+(c&1)

// ===========================================================================
// Prep: fp32 -> fp16 for both inputs in ONE launch
// ===========================================================================
#define APREP_BLKS_PER 32768
__global__ __launch_bounds__(256)
void aprep2_kernel(const float* __restrict__ s0, __half* __restrict__ d0,
                   const float* __restrict__ s1, __half* __restrict__ d1)
{
    const int b = blockIdx.x;
    const float* src = (b < APREP_BLKS_PER) ? s0 : s1;
    __half*      dst = (b < APREP_BLKS_PER) ? d0 : d1;
    const size_t i = ((size_t)(b & (APREP_BLKS_PER - 1)) * 256 + threadIdx.x) * 8;
    const float4 a = *(const float4*)(src + i);
    const float4 c = *(const float4*)(src + i + 4);
    __half2 h[4];
    h[0] = __floats2half2_rn(a.x, a.y);
    h[1] = __floats2half2_rn(a.z, a.w);
    h[2] = __floats2half2_rn(c.x, c.y);
    h[3] = __floats2half2_rn(c.z, c.w);
    *(uint4*)(dst + i) = *(uint4*)h;
}

// ===========================================================================
// Weight prep — fragment-packed fp16, all 4 weights in ONE launch
// ===========================================================================
__global__ __launch_bounds__(256)
void wprep4_kernel(const float* __restrict__ W0, const float* __restrict__ W1,
                   const float* __restrict__ W2, const float* __restrict__ W3,
                   uint32_t* __restrict__ Wf)
{
    const int w   = blockIdx.x >> 9;
    const float* W = (w == 0) ? W0 : (w == 1) ? W1 : (w == 2) ? W2 : W3;
    const int o   = (blockIdx.x & 511) * 256 + threadIdx.x;
    const int rg  = o & 1;
    const int l   = (o >> 1) & 31;
    const int ntg = (o >> 6) & 63;
    const int ks  = (o >> 12) & 3;
    const int c   = o >> 14;
    const int k0  = c * 64 + ks * 16 + (l & 3) * 2 + 8 * rg;
    const int n   = ntg * 8 + (l >> 2);
    Wf[(size_t)w * 131072 + o] =
        packh2(W[(size_t)k0 * EMB + n], W[(size_t)(k0 + 1) * EMB + n]);
}

// ===========================================================================
// Shared GEMM config (validated: 3-stage, 32x64 warp tile)
// ===========================================================================
#define AS_B    144
#define A_STG   (128 * 36)
#define B_STG   4096
#define STG_W   (A_STG + B_STG)
#define GEMM_SMEM (3 * STG_W * 4)     // 104448 B

// ===========================================================================
// Q/K/V projection GEMM with weight offset (for split-stream launches).
// ===========================================================================
__global__ __launch_bounds__(256, 2)
void gemm_qkv_kernel(const __half* __restrict__ iq,
                     const __half* __restrict__ ik,
                     const uint32_t* __restrict__ WfBase,
                     const float* __restrict__ bq,
                     const float* __restrict__ bk,
                     const float* __restrict__ bv,
                     __half* __restrict__ Qo,
                     __half* __restrict__ Ko,
                     __half* __restrict__ Vo,
                     int wofs)
{
    extern __shared__ uint32_t sm[];
    const uint32_t smb = smem_u32(sm);

    const int t   = threadIdx.x;
    const int lid = t & 31;
    const int wid = t >> 5;
    const int wr  = wid >> 1;
    const int wc  = wid & 1;
    const int w   = (blockIdx.x >> 2) + wofs;   // 0..2
    const int bx  = blockIdx.x & 3;
    const int bm  = blockIdx.y * 128;

    const __half* Ah   = (w == 0) ? iq : ik;
    const uint32_t* Wf = WfBase + (size_t)w * 131072;
    const float* bias  = (w == 0) ? bq : (w == 1) ? bk : bv;
    __half* Cv         = (w == 0) ? Qo : (w == 1) ? Ko : Vo;
    const int act      = (w < 2);

    const uint4* W4 = (const uint4*)Wf;

    auto issue = [&](int c, int s) {
        const uint32_t st = smb + (uint32_t)s * (STG_W * 4);
        #pragma unroll
        for (int i = 0; i < 4; i++) {
            const int id  = t + i * 256;
            const int row = id >> 3;
            const int j   = id & 7;
            cp16(st + row * AS_B + j * 16,
                 Ah + (size_t)(bm + row) * EMB + c * 64 + j * 8);
        }
        #pragma unroll
        for (int i = 0; i < 4; i++) {
            const int id   = t + i * 256;
            const int ks   = id >> 8;
            const int rest = id & 255;
            cp16(st + (A_STG + ks * 1024) * 4 + rest * 16,
                 W4 + (size_t)((c * 4 + ks) * 64 + bx * 16) * 16 + rest);
        }
        CP_COMMIT();
    };

    float acc[2][8][4];
    #pragma unroll
    for (int i = 0; i < 2; i++)
        #pragma unroll
        for (int j = 0; j < 8; j++)
            #pragma unroll
            for (int k = 0; k < 4; k++)
                acc[i][j][k] = 0.f;

    issue(0, 0);
    issue(1, 1);

    for (int c = 0; c < 8; c++) {
        const int s = c % 3;
        if (c >= 6) { CP_WAIT0(); } else { CP_WAIT1(); }
        __syncthreads();
        if (c + 2 < 8) issue(c + 2, (c + 2) % 3);

        const uint32_t stA = smb + (uint32_t)s * (STG_W * 4);
        const uint32_t* Bb = sm + s * STG_W + A_STG;

        #pragma unroll
        for (int ks = 0; ks < 4; ks++) {
            uint32_t aF[2][4];
            #pragma unroll
            for (int m2 = 0; m2 < 2; m2++)
                ldmx4(aF[m2], stA + (wr * 32 + m2 * 16 + (lid & 15)) * AS_B
                               + ks * 32 + (lid >> 4) * 16);
            uint32_t bF[8][2];
            #pragma unroll
            for (int n2 = 0; n2 < 8; n2++) {
                const uint2 v = *(const uint2*)
                    &Bb[ks * 1024 + (wc * 8 + n2) * 64 + lid * 2];
                bF[n2][0] = v.x; bF[n2][1] = v.y;
            }
            #pragma unroll
            for (int m2 = 0; m2 < 2; m2++)
                #pragma unroll
                for (int n2 = 0; n2 < 8; n2++)
                    mma16(acc[m2][n2], aF[m2], bF[n2]);
        }
    }

    const int bn = bx * 128;
    const int r0 = bm + wr * 32 + (lid >> 2);
    #pragma unroll
    for (int m2 = 0; m2 < 2; m2++) {
        const int row = r0 + m2 * 16;
        #pragma unroll
        for (int n2 = 0; n2 < 8; n2++) {
            const int col = bn + wc * 64 + n2 * 8 + (lid & 3) * 2;
            const float b0 = __ldg(bias + col);
            const float b1 = __ldg(bias + col + 1);
            float v0 = acc[m2][n2][0] + b0;
            float v1 = acc[m2][n2][1] + b1;
            float v2 = acc[m2][n2][2] + b0;
            float v3 = acc[m2][n2][3] + b1;
            if (act) {
                v0 = elu1(v0); v1 = elu1(v1); v2 = elu1(v2); v3 = elu1(v3);
            }
            *(uint32_t*)(Cv + (size_t)row * EMB + col)       = packh2(v0, v1);
            *(uint32_t*)(Cv + (size_t)(row + 8) * EMB + col) = packh2(v2, v3);
        }
    }
}

// ===========================================================================
// Output-projection GEMM (fp16 in, fp32 out)
// ===========================================================================
__global__ __launch_bounds__(256, 2)
void gemm_out_kernel(const __half* __restrict__ Ah,
                     const uint32_t* __restrict__ Wf,
                     const float* __restrict__ bias,
                     float* __restrict__ Cf)
{
    extern __shared__ uint32_t sm[];
    const uint32_t smb = smem_u32(sm);

    const int t   = threadIdx.x;
    const int lid = t & 31;
    const int wid = t >> 5;
    const int wr  = wid >> 1;
    const int wc  = wid & 1;
    const int bx  = blockIdx.x;
    const int bm  = blockIdx.y * 128;

    const uint4* W4 = (const uint4*)Wf;

    auto issue = [&](int c, int s) {
        const uint32_t st = smb + (uint32_t)s * (STG_W * 4);
        #pragma unroll
        for (int i = 0; i < 4; i++) {
            const int id  = t + i * 256;
            const int row = id >> 3;
            const int j   = id & 7;
            cp16(st + row * AS_B + j * 16,
                 Ah + (size_t)(bm + row) * EMB + c * 64 + j * 8);
        }
        #pragma unroll
        for (int i = 0; i < 4; i++) {
            const int id   = t + i * 256;
            const int ks   = id >> 8;
            const int rest = id & 255;
            cp16(st + (A_STG + ks * 1024) * 4 + rest * 16,
                 W4 + (size_t)((c * 4 + ks) * 64 + bx * 16) * 16 + rest);
        }
        CP_COMMIT();
    };

    float acc[2][8][4];
    #pragma unroll
    for (int i = 0; i < 2; i++)
        #pragma unroll
        for (int j = 0; j < 8; j++)
            #pragma unroll
            for (int k = 0; k < 4; k++)
                acc[i][j][k] = 0.f;

    issue(0, 0);
    issue(1, 1);

    for (int c = 0; c < 8; c++) {
        const int s = c % 3;
        if (c >= 6) { CP_WAIT0(); } else { CP_WAIT1(); }
        __syncthreads();
        if (c + 2 < 8) issue(c + 2, (c + 2) % 3);

        const uint32_t stA = smb + (uint32_t)s * (STG_W * 4);
        const uint32_t* Bb = sm + s * STG_W + A_STG;

        #pragma unroll
        for (int ks = 0; ks < 4; ks++) {
            uint32_t aF[2][4];
            #pragma unroll
            for (int m2 = 0; m2 < 2; m2++)
                ldmx4(aF[m2], stA + (wr * 32 + m2 * 16 + (lid & 15)) * AS_B
                               + ks * 32 + (lid >> 4) * 16);
            uint32_t bF[8][2];
            #pragma unroll
            for (int n2 = 0; n2 < 8; n2++) {
                const uint2 v = *(const uint2*)
                    &Bb[ks * 1024 + (wc * 8 + n2) * 64 + lid * 2];
                bF[n2][0] = v.x; bF[n2][1] = v.y;
            }
            #pragma unroll
            for (int m2 = 0; m2 < 2; m2++)
                #pragma unroll
                for (int n2 = 0; n2 < 8; n2++)
                    mma16(acc[m2][n2], aF[m2], bF[n2]);
        }
    }

    const int bn = bx * 128;
    const int r0 = bm + wr * 32 + (lid >> 2);
    #pragma unroll
    for (int m2 = 0; m2 < 2; m2++) {
        const int row = r0 + m2 * 16;
        #pragma unroll
        for (int n2 = 0; n2 < 8; n2++) {
            const int col = bn + wc * 64 + n2 * 8 + (lid & 3) * 2;
            const float b0 = __ldg(bias + col);
            const float b1 = __ldg(bias + col + 1);
            float2 o0; o0.x = acc[m2][n2][0] + b0; o0.y = acc[m2][n2][1] + b1;
            float2 o1; o1.x = acc[m2][n2][2] + b0; o1.y = acc[m2][n2][3] + b1;
            *(float2*)(Cf + (size_t)row * EMB + col) = o0;
            *(float2*)(Cf + (size_t)(row + 8) * EMB + col) = o1;
        }
    }
}

// ===========================================================================
// Tensorized KtV + ksum -> packed fp16 output g_KtVh[g][d2][e]  (validated)
// ===========================================================================
#define KTV_KST   9216
#define KTV_VST   11264
#define KTV_STG   (KTV_KST + KTV_VST)
#define KTV_SMEM  (3 * KTV_STG)

__global__ __launch_bounds__(256)
void ktv_mma_kernel(const __half* __restrict__ Kp,
                    const __half* __restrict__ Vp,
                    uint32_t* __restrict__ KtVh)
{
    extern __shared__ uint32_t sm[];
    const uint32_t smb = smem_u32(sm);

    const int g  = blockIdx.x;
    const int bs = g >> 3;
    const int h  = g & 7;
    const size_t rowbase = (size_t)bs * ALEN;
    const int coff = h * HDIM;

    const int t   = threadIdx.x;
    const int lid = t & 31;
    const int wid = t >> 5;
    const int mt  = wid >> 1;
    const int nh  = wid & 1;
    const int ntc = 5 - nh;
    const int n0  = nh * 40;

    if (t < 64) {
        #pragma unroll
        for (int s = 0; s < 3; s++) {
            __half* vb = (__half*)((char*)sm + s * KTV_STG + KTV_KST);
            vb[t * 88 + 64] = __float2half(1.0f);
        }
    }

    auto issue = [&](int c, int s) {
        const uint32_t stK = smb + (uint32_t)s * KTV_STG;
        const uint32_t stV = stK + KTV_KST;
        const int a0 = c * 64;
        #pragma unroll
        for (int i = 0; i < 2; i++) {
            const int id  = t + i * 256;
            const int row = id >> 3;
            const int j   = id & 7;
            const size_t goff = (rowbase + a0 + row) * EMB + coff + j * 8;
            cp16(stK + row * 144 + j * 16, Kp + goff);
            cp16(stV + row * 176 + j * 16, Vp + goff);
        }
        CP_COMMIT();
    };

    float acc[5][4];
    #pragma unroll
    for (int i = 0; i < 5; i++)
        #pragma unroll
        for (int j = 0; j < 4; j++)
            acc[i][j] = 0.f;

    const int g2 = lid >> 3;
    const int l8 = lid & 7;
    const int a_rowA = (g2 >> 1) * 8 + l8;
    const int a_colA = mt * 16 + (g2 & 1) * 8;
    const int a_rowB = (g2 & 1) * 8 + l8;
    const int a_colB = (g2 >> 1) * 8;
    const int a_rowB2 = ((lid >> 3) & 1) * 8 + l8;

    issue(0, 0);
    issue(1, 1);

    for (int c = 0; c < 32; c++) {
        const int s = c % 3;
        if (c >= 30) { CP_WAIT0(); } else { CP_WAIT1(); }
        __syncthreads();
        if (c + 2 < 32) issue(c + 2, (c + 2) % 3);

        const uint32_t stK = smb + (uint32_t)s * KTV_STG;
        const uint32_t stV = stK + KTV_KST;

        #pragma unroll
        for (int ks = 0; ks < 4; ks++) {
            uint32_t aF[4];
            ldmx4t(aF, stK + (ks * 16 + a_rowA) * 144 + a_colA * 2);

            uint32_t bF[5][2];
            {
                uint32_t r4[4];
                ldmx4t(r4, stV + (ks * 16 + a_rowB) * 176 + (n0 + a_colB) * 2);
                bF[0][0] = r4[0]; bF[0][1] = r4[1];
                bF[1][0] = r4[2]; bF[1][1] = r4[3];
                ldmx4t(r4, stV + (ks * 16 + a_rowB) * 176 + (n0 + 16 + a_colB) * 2);
                bF[2][0] = r4[0]; bF[2][1] = r4[1];
                bF[3][0] = r4[2]; bF[3][1] = r4[3];
            }
            if (nh == 0) {
                uint32_t r2[2];
                ldmx2t(r2, stV + (ks * 16 + a_rowB2) * 176 + (n0 + 32) * 2);
                bF[4][0] = r2[0]; bF[4][1] = r2[1];
            }

            #pragma unroll
            for (int nt = 0; nt < 4; nt++)
                mma16(acc[nt], aF, bF[nt]);
            if (nh == 0)
                mma16(acc[4], aF, bF[4]);
        }
    }

    uint32_t* Kout = KtVh + (size_t)g * 2304;
    const int r2 = lid >> 2;
    #pragma unroll
    for (int nt = 0; nt < 5; nt++) {
        if (nt >= ntc) break;
        const int n = n0 + nt * 8;
        #pragma unroll
        for (int c = 0; c < 4; c++) {
            const float v  = acc[nt][c];
            const float vo = __shfl_xor_sync(0xffffffffu, v, 4);
            if ((r2 & 1) == 0) {
                const int d2 = mt * 8 + (r2 >> 1) + 4 * (c >> 1);
                const int e  = n + (lid & 3) * 2 + (c & 1);
                if (e <= 64) Kout[d2 * 72 + e] = packh2(v, vo);
            }
        }
    }
    if (t < 224) Kout[(t / 7) * 72 + 65 + (t % 7)] = 0u;
}

// ===========================================================================
// fp16 tensorized apply — reads PACKED KtVh (plain copy into smem).
// ===========================================================================
#define AQ_B  144
#define SM_S  72
#define APPLY_SMEM ((128 * 36 + 32 * SM_S) * 4)   // 27648 B

__global__ __launch_bounds__(256, 4)
void apply_h_kernel(const __half* __restrict__ Qp,
                    const uint32_t* __restrict__ KtVh,
                    __half* __restrict__ AO)
{
    extern __shared__ uint32_t sm[];
    const uint32_t sQb = smem_u32(sm);
    uint32_t* sM = sm + 128 * 36;

    const int g    = blockIdx.y;
    const int tile = blockIdx.x;
    const int bs   = g >> 3;
    const int h    = g & 7;
    const int t    = threadIdx.x;
    const int lid  = t & 31;
    const int wid  = t >> 5;

    {
        const uint32_t* src = KtVh + (size_t)g * 2304;
        #pragma unroll
        for (int i = t; i < 2304; i += 256) sM[i] = src[i];
    }
    {
        #pragma unroll
        for (int i = 0; i < 4; i++) {
            const int id  = t + i * 256;
            const int row = id >> 3;
            const int j   = id & 7;
            const uint4 v = *(const uint4*)
                (Qp + ((size_t)bs * ALEN + tile * 128 + row) * EMB + h * HDIM + j * 8);
            *(uint4*)((char*)sm + row * AQ_B + j * 16) = v;
        }
    }
    __syncthreads();

    float acc[9][4];
    #pragma unroll
    for (int i = 0; i < 9; i++)
        #pragma unroll
        for (int j = 0; j < 4; j++)
            acc[i][j] = 0.f;

    #pragma unroll
    for (int ks = 0; ks < 4; ks++) {
        uint32_t aF[4];
        ldmx4(aF, sQb + (wid * 16 + (lid & 15)) * AQ_B + ks * 32 + (lid >> 4) * 16);
        #pragma unroll
        for (int n2 = 0; n2 < 9; n2++) {
            uint32_t bF[2];
            const int n = n2 * 8 + (lid >> 2);
            bF[0] = sM[(ks * 8 + (lid & 3)) * SM_S + n];
            bF[1] = sM[(ks * 8 + 4 + (lid & 3)) * SM_S + n];
            mma16(acc[n2], aF, bF);
        }
    }

    const float den0 = __shfl_sync(0xffffffffu, acc[8][0], lid & ~3);
    const float den1 = __shfl_sync(0xffffffffu, acc[8][2], lid & ~3);
    const float z0 = 1.f / (den0 + EPS_F);
    const float z1 = 1.f / (den1 + EPS_F);

    const int arow = tile * 128 + wid * 16 + (lid >> 2);
    const size_t base = ((size_t)bs * ALEN + arow) * EMB + h * HDIM;
    #pragma unroll
    for (int n2 = 0; n2 < 8; n2++) {
        const int col = n2 * 8 + (lid & 3) * 2;
        *(uint32_t*)(AO + base + col) = packh2(z0 * acc[n2][0], z0 * acc[n2][1]);
        *(uint32_t*)(AO + base + (size_t)8 * EMB + col) =
            packh2(z1 * acc[n2][2], z1 * acc[n2][3]);
    }
}

// ---------------------------------------------------------------------------
extern "C" void kernel_launch(void* const* d_in, const int* in_sizes, int n_in,
                              void* d_out, int out_size)
{
    const float* input_q  = (const float*)d_in[0];
    const float* input_kv = (const float*)d_in[1];
    const float* Wq = (const float*)d_in[2];
    const float* bq = (const float*)d_in[3];
    const float* Wk = (const float*)d_in[4];
    const float* bk = (const float*)d_in[5];
    const float* Wv = (const float*)d_in[6];
    const float* bv = (const float*)d_in[7];
    const float* Wo = (const float*)d_in[8];
    const float* bo = (const float*)d_in[9];
    float* out = (float*)d_out;

    void *p0, *p1, *p2, *p3, *p4, *p5, *p8, *p10;
    cudaGetSymbolAddress(&p0,  g_iqh);
    cudaGetSymbolAddress(&p1,  g_ikh);
    cudaGetSymbolAddress(&p2,  g_Qh);
    cudaGetSymbolAddress(&p3,  g_Kh);
    cudaGetSymbolAddress(&p4,  g_Vh);
    cudaGetSymbolAddress(&p5,  g_AOh);
    cudaGetSymbolAddress(&p8,  g_KtVh);
    cudaGetSymbolAddress(&p10, g_Wf);
    __half*   iqh  = (__half*)p0;
    __half*   ikh  = (__half*)p1;
    __half*   Qh   = (__half*)p2;
    __half*   Kh   = (__half*)p3;
    __half*   Vh   = (__half*)p4;
    __half*   AOh  = (__half*)p5;
    uint32_t* KtVh = (uint32_t*)p8;
    uint32_t* Wf   = (uint32_t*)p10;

    cudaFuncSetAttribute((const void*)gemm_qkv_kernel,
                         cudaFuncAttributeMaxDynamicSharedMemorySize, GEMM_SMEM);
    cudaFuncSetAttribute((const void*)gemm_out_kernel,
                         cudaFuncAttributeMaxDynamicSharedMemorySize, GEMM_SMEM);
    cudaFuncSetAttribute((const void*)ktv_mma_kernel,
                         cudaFuncAttributeMaxDynamicSharedMemorySize, KTV_SMEM);
    cudaFuncSetAttribute((const void*)apply_h_kernel,
                         cudaFuncAttributeMaxDynamicSharedMemorySize, APPLY_SMEM);
    // Max shared carveout: try to unlock 2 CTAs/SM for the GEMMs
    cudaFuncSetAttribute((const void*)gemm_qkv_kernel,
                         cudaFuncAttributePreferredSharedMemoryCarveout, 100);
    cudaFuncSetAttribute((const void*)gemm_out_kernel,
                         cudaFuncAttributePreferredSharedMemoryCarveout, 100);

    const size_t WSZ = 131072;

    // Side stream + events (created fresh per call; no device memory)
    cudaStream_t s2;
    cudaStreamCreateWithFlags(&s2, cudaStreamNonBlocking);
    cudaEvent_t eKV, eK;
    cudaEventCreateWithFlags(&eKV, cudaEventDisableTiming);
    cudaEventCreateWithFlags(&eK,  cudaEventDisableTiming);

    // stream0: preps -> KV GEMM -> (eKV) -> Q GEMM
    wprep4_kernel<<<2048, 256>>>(Wq, Wk, Wv, Wo, Wf);
    aprep2_kernel<<<2 * APREP_BLKS_PER, 256>>>(input_q, iqh, input_kv, ikh);

    gemm_qkv_kernel<<<dim3(8, M_TOK / 128), 256, GEMM_SMEM>>>(
        iqh, ikh, Wf, bq, bk, bv, Qh, Kh, Vh, /*wofs=*/1);   // K, V
    cudaEventRecord(eKV, 0);

    gemm_qkv_kernel<<<dim3(4, M_TOK / 128), 256, GEMM_SMEM>>>(
        iqh, ikh, Wf, bq, bk, bv, Qh, Kh, Vh, /*wofs=*/0);   // Q

    // s2: ktv runs concurrently with the Q projection
    cudaStreamWaitEvent(s2, eKV, 0);
    ktv_mma_kernel<<<NGROUP, 256, KTV_SMEM, s2>>>(Kh, Vh, KtVh);
    cudaEventRecord(eK, s2);

    // join: apply needs Q (stream0 order) and KtVh (eK)
    cudaStreamWaitEvent(0, eK, 0);
    apply_h_kernel<<<dim3(ALEN / 128, NGROUP), 256, APPLY_SMEM>>>(Qh, KtVh, AOh);

    // Output projection (fp32 out)
    gemm_out_kernel<<<dim3(4, M_TOK / 128), 256, GEMM_SMEM>>>(
        AOh, Wf + 3 * WSZ, bo, out);
}